// round 17
// baseline (speedup 1.0000x reference)
#include <cuda_runtime.h>
#include <cuda_fp16.h>
#include <cstdint>

#define NN 50000
#define EE 400000
#define TT 3
#define KD 256
#define HH 8
#define HD 32
#define CAP 64   // max in-degree bucket (Poisson(8): max~26, huge margin)

// ---- scratch (device globals; no allocs allowed) ----
__device__ __half g_h[TT * NN * KD];     // per-type transformed features (fp16 storage)
__device__ float g_sl[TT * NN * HH];
__device__ float g_sr[TT * NN * HH];
__device__ int   g_cnt[TT * NN];
__device__ int   g_adj[TT * NN * CAP];
__device__ __half g_xh[NN * KD];         // x (fp16 rn)
__device__ __half g_Wh[TT * KD * KD];    // W^T (fp16 rn)  [t][n][k]

static __device__ __forceinline__ uint32_t s2u(const void* p) {
    uint32_t a;
    asm("{ .reg .u64 t; cvta.to.shared.u64 t, %1; cvt.u32.u64 %0, t; }" : "=r"(a) : "l"(p));
    return a;
}
static __device__ __forceinline__ void cp16(uint32_t dst, const void* src, int sz) {
    asm volatile("cp.async.cg.shared.global [%0], [%1], 16, %2;"
                 :: "r"(dst), "l"(src), "r"(sz) : "memory");
}
static __device__ __forceinline__ void ldsm4(uint32_t* r, uint32_t addr) {
    asm volatile("ldmatrix.sync.aligned.m8n8.x4.shared.b16 {%0,%1,%2,%3}, [%4];"
                 : "=r"(r[0]), "=r"(r[1]), "=r"(r[2]), "=r"(r[3]) : "r"(addr));
}
static __device__ __forceinline__ void mma16(float* c, const uint32_t* a,
                                             uint32_t b0, uint32_t b1) {
    asm volatile(
        "mma.sync.aligned.m16n8k16.row.col.f32.f16.f16.f32 "
        "{%0,%1,%2,%3},{%4,%5,%6,%7},{%8,%9},{%0,%1,%2,%3};"
        : "+f"(c[0]), "+f"(c[1]), "+f"(c[2]), "+f"(c[3])
        : "r"(a[0]), "r"(a[1]), "r"(a[2]), "r"(a[3]), "r"(b0), "r"(b1));
}

// ---------------- prep: bucketed CSR build ----------------
__global__ void build_kernel(const int* __restrict__ ei) {
    int i = blockIdx.x * blockDim.x + threadIdx.x;
    if (i >= TT * EE) return;
    int t = i / EE, e = i - t * EE;
    int s = ei[t * 2 * EE + e];
    int d = ei[t * 2 * EE + EE + e];
    int pos = atomicAdd(&g_cnt[t * NN + d], 1);
    if (pos < CAP) g_adj[(t * NN + d) * CAP + pos] = s;
}

// ---------------- prep: fp16 conversion of x, W^T; zero counters (fused) ----------------
__global__ void convert_kernel(const float* __restrict__ x, const float* __restrict__ W) {
    int i = blockIdx.x * blockDim.x + threadIdx.x;
    if (i < NN * KD) {
        g_xh[i] = __float2half_rn(x[i]);
    } else if (i < NN * KD + TT * KD * KD) {
        int j = i - NN * KD;
        int n = j & 255, k = (j >> 8) & 255, t = j >> 16;
        g_Wh[(t << 16) + (n << 8) + k] = __float2half_rn(W[j]);
    } else if (i < NN * KD + TT * KD * KD + TT * NN) {
        g_cnt[i - NN * KD - TT * KD * KD] = 0;
    }
}

// ---------------- fp16 mma.sync GEMM + fused score epilogue ----------------
// CTA 128x128xK256, BK=64 (4 iterations), 256 thr, 8 warps 2x4, warp tile 64x32,
// 2 CTAs/SM. Fragment loads via ldmatrix.x4. SMEM rows: 64 halves at stride 36
// words — LDSM phase conflict-free. Double-buffered cp.async.
#define ROW_W 36
#define PLANE_W (128 * ROW_W)
#define BUF_W (2 * PLANE_W)
#define SM_TOTAL (2 * BUF_W * 4)       // 73728 B

__global__ void __launch_bounds__(256, 2) gemm_scores_kernel(const float* __restrict__ a_l,
                                                             const float* __restrict__ a_r) {
    extern __shared__ char smraw[];
    const uint32_t sbase = s2u(smraw);

    const int tid = threadIdx.x;
    const int wid = tid >> 5, lane = tid & 31;
    const int g = lane >> 2, tg = lane & 3;
    const int wr = wid >> 2, wc = wid & 3;
    const int t = blockIdx.z;
    const int m0 = blockIdx.x * 128, n0 = blockIdx.y * 128;

    float acc[4][4][4];
#pragma unroll
    for (int i = 0; i < 4; i++)
#pragma unroll
        for (int j = 0; j < 4; j++)
#pragma unroll
            for (int q = 0; q < 4; q++) acc[i][j][q] = 0.f;

    const int a_row = wr * 64 + (lane & 15);
    const uint32_t a_koff = (uint32_t)((lane >> 4) << 2);
    const int b_row = wc * 32 + ((lane & 7) | ((lane >> 4) << 3));
    const uint32_t b_koff = (uint32_t)(((lane >> 3) & 1) << 2);

    auto loadTile = [&](int kt, int buf) {
        const int k0 = kt * 64;
        uint32_t sb = sbase + (uint32_t)buf * BUF_W * 4;
#pragma unroll
        for (int j = 0; j < 4; j++) {
            int c = tid + j * 256;
            int r = c >> 3, q = c & 7;
            uint32_t wo = (uint32_t)(r * ROW_W + q * 4) * 4;
            int gr = m0 + r;
            cp16(sb + wo, g_xh + (size_t)gr * KD + k0 + q * 8, gr < NN ? 16 : 0);
            cp16(sb + PLANE_W * 4 + wo,
                 g_Wh + ((size_t)t * KD + n0 + r) * KD + k0 + q * 8, 16);
        }
        asm volatile("cp.async.commit_group;" ::: "memory");
    };

    loadTile(0, 0);

    for (int kt = 0; kt < 4; kt++) {
        const int buf = kt & 1;
        if (kt < 3) loadTile(kt + 1, buf ^ 1);
        if (kt < 3) asm volatile("cp.async.wait_group 1;" ::: "memory");
        else        asm volatile("cp.async.wait_group 0;" ::: "memory");
        __syncthreads();

        const uint32_t abase = sbase + (uint32_t)buf * BUF_W * 4;
        const uint32_t bbase = abase + PLANE_W * 4;

#pragma unroll
        for (int ks = 0; ks < 4; ks++) {
            const uint32_t ko = ks * 8;
            uint32_t ah[4][4];
#pragma unroll
            for (int mf = 0; mf < 4; mf++)
                ldsm4(ah[mf], abase + ((uint32_t)(a_row + mf * 16) * ROW_W + ko + a_koff) * 4);
#pragma unroll
            for (int pair = 0; pair < 2; pair++) {
                uint32_t bb[4];
                ldsm4(bb, bbase + ((uint32_t)(b_row + pair * 16) * ROW_W + ko + b_koff) * 4);
#pragma unroll
                for (int mf = 0; mf < 4; mf++)
                    mma16(acc[mf][2 * pair], ah[mf], bb[0], bb[1]);
#pragma unroll
                for (int mf = 0; mf < 4; mf++)
                    mma16(acc[mf][2 * pair + 1], ah[mf], bb[2], bb[3]);
            }
        }
        __syncthreads();
    }

    // ---- epilogue: store h (fp16), compute per-head attention scores (fp32) ----
    const int head = blockIdx.y * 4 + wc;
    float wl[4][2], wrt[4][2];
#pragma unroll
    for (int nf = 0; nf < 4; nf++) {
        int lc = nf * 8 + tg * 2;
        wl[nf][0]  = __ldg(a_l + ((size_t)t * HH + head) * HD + lc);
        wl[nf][1]  = __ldg(a_l + ((size_t)t * HH + head) * HD + lc + 1);
        wrt[nf][0] = __ldg(a_r + ((size_t)t * HH + head) * HD + lc);
        wrt[nf][1] = __ldg(a_r + ((size_t)t * HH + head) * HD + lc + 1);
    }
#pragma unroll
    for (int mf = 0; mf < 4; mf++) {
        int r0 = m0 + wr * 64 + mf * 16 + g;
        int r1 = r0 + 8;
        float dl0 = 0.f, dr0 = 0.f, dl1 = 0.f, dr1 = 0.f;
#pragma unroll
        for (int nf = 0; nf < 4; nf++) {
            int col = n0 + wc * 32 + nf * 8 + tg * 2;
            float c0 = acc[mf][nf][0], c1 = acc[mf][nf][1];
            float c2 = acc[mf][nf][2], c3 = acc[mf][nf][3];
            dl0 += c0 * wl[nf][0] + c1 * wl[nf][1];
            dr0 += c0 * wrt[nf][0] + c1 * wrt[nf][1];
            dl1 += c2 * wl[nf][0] + c3 * wl[nf][1];
            dr1 += c2 * wrt[nf][0] + c3 * wrt[nf][1];
            if (r0 < NN)
                *(__half2*)&g_h[((size_t)t * NN + r0) * KD + col] =
                    __floats2half2_rn(c0, c1);
            if (r1 < NN)
                *(__half2*)&g_h[((size_t)t * NN + r1) * KD + col] =
                    __floats2half2_rn(c2, c3);
        }
#pragma unroll
        for (int o = 1; o <= 2; o <<= 1) {
            dl0 += __shfl_xor_sync(0xffffffffu, dl0, o);
            dr0 += __shfl_xor_sync(0xffffffffu, dr0, o);
            dl1 += __shfl_xor_sync(0xffffffffu, dl1, o);
            dr1 += __shfl_xor_sync(0xffffffffu, dr1, o);
        }
        if (tg == 0) {
            if (r0 < NN) {
                g_sl[((size_t)t * NN + r0) * HH + head] = dl0;
                g_sr[((size_t)t * NN + r0) * HH + head] = dr0;
            }
            if (r1 < NN) {
                g_sl[((size_t)t * NN + r1) * HH + head] = dl1;
                g_sr[((size_t)t * NN + r1) * HH + head] = dr1;
            }
        }
    }
}

// ---------------- fused gather-aggregate + semantic attention ----------------
// One warp per (node, TYPE): 3x the gather parallelism vs warp-per-node.
// 192-thread blocks = 6 warps = 2 nodes. Per-type results exchanged via SMEM;
// the t=0 warp of each node does the semantic combine (math order identical).
__global__ void __launch_bounds__(192) agg_sem_kernel(const float* __restrict__ att_w,
                                                      const float* __restrict__ att_b,
                                                      float* __restrict__ out) {
    __shared__ float4 smA[6 * 32];
    __shared__ float4 smB[6 * 32];

    int w = threadIdx.x >> 5, lane = threadIdx.x & 31;
    int nodeSlot = w / 3;                 // 0 or 1
    int t = w - nodeSlot * 3;
    int n = blockIdx.x * 2 + nodeSlot;    // 2*25000 = 50000 exact
    int head = lane >> 2;

    // ---- gather-aggregate for (n, t) ----
    float srv = g_sr[((size_t)t * NN + n) * HH + head];
    int cnt = g_cnt[t * NN + n];
    cnt = cnt < CAP ? cnt : CAP;
    const int* adj = g_adj + ((size_t)t * NN + n) * CAP;
    float4 a0 = make_float4(0.f, 0.f, 0.f, 0.f);
    float4 a1 = make_float4(0.f, 0.f, 0.f, 0.f);
    float den = 0.f;
    int e = 0;
    for (; e + 4 <= cnt; e += 4) {
        int4 s4 = *(const int4*)(adj + e);
        float sc0 = __ldg(g_sl + ((size_t)t * NN + s4.x) * HH + head) + srv;
        float sc1 = __ldg(g_sl + ((size_t)t * NN + s4.y) * HH + head) + srv;
        float sc2 = __ldg(g_sl + ((size_t)t * NN + s4.z) * HH + head) + srv;
        float sc3 = __ldg(g_sl + ((size_t)t * NN + s4.w) * HH + head) + srv;
        uint4 r0v = *(const uint4*)(g_h + ((size_t)t * NN + s4.x) * KD + lane * 8);
        uint4 r1v = *(const uint4*)(g_h + ((size_t)t * NN + s4.y) * KD + lane * 8);
        uint4 r2v = *(const uint4*)(g_h + ((size_t)t * NN + s4.z) * KD + lane * 8);
        uint4 r3v = *(const uint4*)(g_h + ((size_t)t * NN + s4.w) * KD + lane * 8);
        sc0 = sc0 > 0.f ? sc0 : 0.2f * sc0;
        sc1 = sc1 > 0.f ? sc1 : 0.2f * sc1;
        sc2 = sc2 > 0.f ? sc2 : 0.2f * sc2;
        sc3 = sc3 > 0.f ? sc3 : 0.2f * sc3;
        float x0 = __expf(sc0), x1 = __expf(sc1), x2 = __expf(sc2), x3 = __expf(sc3);
        den += (x0 + x1) + (x2 + x3);
        const __half2* h0 = (const __half2*)&r0v;
        const __half2* h1 = (const __half2*)&r1v;
        const __half2* h2 = (const __half2*)&r2v;
        const __half2* h3 = (const __half2*)&r3v;
        float2 f;
        f = __half22float2(h0[0]); a0.x += x0 * f.x; a0.y += x0 * f.y;
        f = __half22float2(h0[1]); a0.z += x0 * f.x; a0.w += x0 * f.y;
        f = __half22float2(h0[2]); a1.x += x0 * f.x; a1.y += x0 * f.y;
        f = __half22float2(h0[3]); a1.z += x0 * f.x; a1.w += x0 * f.y;
        f = __half22float2(h1[0]); a0.x += x1 * f.x; a0.y += x1 * f.y;
        f = __half22float2(h1[1]); a0.z += x1 * f.x; a0.w += x1 * f.y;
        f = __half22float2(h1[2]); a1.x += x1 * f.x; a1.y += x1 * f.y;
        f = __half22float2(h1[3]); a1.z += x1 * f.x; a1.w += x1 * f.y;
        f = __half22float2(h2[0]); a0.x += x2 * f.x; a0.y += x2 * f.y;
        f = __half22float2(h2[1]); a0.z += x2 * f.x; a0.w += x2 * f.y;
        f = __half22float2(h2[2]); a1.x += x2 * f.x; a1.y += x2 * f.y;
        f = __half22float2(h2[3]); a1.z += x2 * f.x; a1.w += x2 * f.y;
        f = __half22float2(h3[0]); a0.x += x3 * f.x; a0.y += x3 * f.y;
        f = __half22float2(h3[1]); a0.z += x3 * f.x; a0.w += x3 * f.y;
        f = __half22float2(h3[2]); a1.x += x3 * f.x; a1.y += x3 * f.y;
        f = __half22float2(h3[3]); a1.z += x3 * f.x; a1.w += x3 * f.y;
    }
    for (; e < cnt; e++) {
        int s0 = __ldg(adj + e);
        float sc0 = __ldg(g_sl + ((size_t)t * NN + s0) * HH + head) + srv;
        uint4 rv = *(const uint4*)(g_h + ((size_t)t * NN + s0) * KD + lane * 8);
        sc0 = sc0 > 0.f ? sc0 : 0.2f * sc0;
        float x0 = __expf(sc0);
        den += x0;
        const __half2* hp = (const __half2*)&rv;
        float2 f;
        f = __half22float2(hp[0]); a0.x += x0 * f.x; a0.y += x0 * f.y;
        f = __half22float2(hp[1]); a0.z += x0 * f.x; a0.w += x0 * f.y;
        f = __half22float2(hp[2]); a1.x += x0 * f.x; a1.y += x0 * f.y;
        f = __half22float2(hp[3]); a1.z += x0 * f.x; a1.w += x0 * f.y;
    }
    float inv = den > 0.f ? __frcp_rn(den) : 1.f;
    smA[w * 32 + lane] = make_float4(a0.x * inv, a0.y * inv, a0.z * inv, a0.w * inv);
    smB[w * 32 + lane] = make_float4(a1.x * inv, a1.y * inv, a1.z * inv, a1.w * inv);

    __syncthreads();

    // ---- semantic attention (t==0 warp of each node) ----
    if (t == 0) {
        float4 w0 = ((const float4*)att_w)[lane * 2];
        float4 w1 = ((const float4*)att_w)[lane * 2 + 1];
        float b = att_b[0];
        float4 acc0 = make_float4(0.f, 0.f, 0.f, 0.f);
        float4 acc1 = make_float4(0.f, 0.f, 0.f, 0.f);
#pragma unroll
        for (int tt = 0; tt < TT; tt++) {
            float4 o0 = smA[(w + tt) * 32 + lane];
            float4 o1 = smB[(w + tt) * 32 + lane];
            float p = o0.x * w0.x + o0.y * w0.y + o0.z * w0.z + o0.w * w0.w
                    + o1.x * w1.x + o1.y * w1.y + o1.z * w1.z + o1.w * w1.w;
#pragma unroll
            for (int o = 16; o; o >>= 1) p += __shfl_xor_sync(0xffffffffu, p, o);
            float att = p + b;
            acc0.x += att * o0.x; acc0.y += att * o0.y;
            acc0.z += att * o0.z; acc0.w += att * o0.w;
            acc1.x += att * o1.x; acc1.y += att * o1.y;
            acc1.z += att * o1.z; acc1.w += att * o1.w;
        }
        float4* dp = (float4*)(out + (size_t)n * KD + lane * 8);
        dp[0] = acc0;
        dp[1] = acc1;
    }
}

extern "C" void kernel_launch(void* const* d_in, const int* in_sizes, int n_in,
                              void* d_out, int out_size) {
    const float* x     = (const float*)d_in[0];
    const int*   ei    = (const int*)d_in[1];
    const float* W     = (const float*)d_in[2];
    const float* a_l   = (const float*)d_in[3];
    const float* a_r   = (const float*)d_in[4];
    const float* att_w = (const float*)d_in[5];
    const float* att_b = (const float*)d_in[6];
    float* out = (float*)d_out;

    static int smem_set = 0;
    if (!smem_set) {
        cudaFuncSetAttribute(gemm_scores_kernel,
                             cudaFuncAttributeMaxDynamicSharedMemorySize, SM_TOTAL);
        smem_set = 1;
    }

    int convN = NN * KD + TT * KD * KD + TT * NN;
    convert_kernel<<<(convN + 255) / 256, 256>>>(x, W);
    build_kernel<<<(TT * EE + 255) / 256, 256>>>(ei);

    dim3 ggrid((NN + 127) / 128, 2, TT);
    gemm_scores_kernel<<<ggrid, 256, SM_TOTAL>>>(a_l, a_r);

    agg_sem_kernel<<<NN / 2, 192>>>(att_w, att_b, out);
}